// round 13
// baseline (speedup 1.0000x reference)
#include <cuda_runtime.h>

// Chamfer distance, B=2, N=8192. Symmetric: each pair computed once, feeds both
// row-min (per-gt) and col-min (per-pred). w = c_i + c_j - q.p, c = 0.5||.||^2.
// Dual-order f32x2 pass (unchanged from R12). Reduce rebuilt: float4 tasks with
// explicit MLP-11 load batching; done-counter final sum (2 launches).

#define BATCH   2
#define NPTS    8192
#define THREADS 256
#define QPT     8                    // queries per thread
#define NGRP    (QPT / 2)            // 4 packed query groups
#define IBLK    (THREADS * QPT)      // 2048 gt rows per CTA
#define ITILES  (NPTS / IBLK)        // 4
#define JSPLITS 55
#define TOTP    (NPTS / 2)           // 4096 pred pairs per batch
#define MAXP    75                   // ceil(4096/55)
#define NCTA    (BATCH * ITILES * JSPLITS)   // 440 <= 444 @3/SM -> one wave
#define RBLOCKS 64

__device__ float    g_rowpart[BATCH * JSPLITS * NPTS];   // 3.6 MB
__device__ float    g_colpart[BATCH * ITILES  * NPTS];   // 0.25 MB
__device__ float    g_blocksum[RBLOCKS];
__device__ unsigned g_done;          // zero-init; self-resets each call

typedef unsigned long long u64;

__device__ __forceinline__ u64 pack2(float lo, float hi) {
    u64 d; asm("mov.b64 %0, {%1,%2};" : "=l"(d) : "f"(lo), "f"(hi)); return d;
}
__device__ __forceinline__ void unpack2(u64 d, float& lo, float& hi) {
    asm("mov.b64 {%0,%1}, %2;" : "=f"(lo), "=f"(hi) : "l"(d));
}
__device__ __forceinline__ u64 fma2(u64 a, u64 b, u64 c) {
    u64 d; asm("fma.rn.f32x2 %0, %1, %2, %3;" : "=l"(d) : "l"(a), "l"(b), "l"(c));
    return d;
}
__device__ __forceinline__ u64 add2(u64 a, u64 b) {
    u64 d; asm("add.rn.f32x2 %0, %1, %2;" : "=l"(d) : "l"(a), "l"(b));
    return d;
}

__global__ __launch_bounds__(THREADS, 3)
void chamfer_pass(const float* __restrict__ pred, const float* __restrict__ gt) {
    const int bid = blockIdx.x;
    const int b   = bid / (ITILES * JSPLITS);
    const int r   = bid - b * (ITILES * JSPLITS);
    const int it  = r / JSPLITS;
    const int js  = r - it * JSPLITS;
    const int ibase  = it * IBLK;
    const int pstart = (js * TOTP) / JSPLITS;
    const int pend   = ((js + 1) * TOTP) / JSPLITS;
    const int npairs = pend - pstart;           // 74 or 75 (>= 32 for lane-skew)
    const int tid = threadIdx.x;

    // 16B-stride arrays (conflict-free under lane-consecutive jp):
    __shared__ float4 sXY1[MAXP];   // {x0,x1,y0,y1}
    __shared__ float4 sZC1[MAXP];   // {z0,z1,c0,c1}
    __shared__ float4 sXY2[MAXP];   // {x1,x0,y1,y0}
    __shared__ float4 sZC2[MAXP];   // {z1,z0,c1,c0}
    __shared__ float2 scm[THREADS / 32][MAXP]; // per-warp col-min {p0,p1}

    if (tid < npairs) {
        const float* p = pred + ((size_t)b * NPTS + 2 * (pstart + tid)) * 3;
        float x0 = p[0], y0 = p[1], z0 = p[2];
        float x1 = p[3], y1 = p[4], z1 = p[5];
        float c0 = 0.5f * (x0 * x0 + y0 * y0 + z0 * z0);
        float c1 = 0.5f * (x1 * x1 + y1 * y1 + z1 * z1);
        sXY1[tid] = make_float4(x0, x1, y0, y1);
        sZC1[tid] = make_float4(z0, z1, c0, c1);
        sXY2[tid] = make_float4(x1, x0, y1, y0);
        sZC2[tid] = make_float4(z1, z0, c1, c0);
    }
    if (tid < MAXP) {
#pragma unroll
        for (int u = 0; u < THREADS / 32; u++)
            scm[u][tid] = make_float2(3.4e38f, 3.4e38f);
    }

    // Queries (gt): two different queries per u64 (A = slot 2g, B = slot 2g+1).
    u64 qx2[NGRP], qy2[NGRP], qz2[NGRP], qc2[NGRP];
    float rm[QPT];
#pragma unroll
    for (int g = 0; g < NGRP; g++) {
        const float* qa = gt + ((size_t)b * NPTS + ibase + tid + (2 * g) * THREADS) * 3;
        const float* qb = gt + ((size_t)b * NPTS + ibase + tid + (2 * g + 1) * THREADS) * 3;
        float xa = qa[0], ya = qa[1], za = qa[2];
        float xb = qb[0], yb = qb[1], zb = qb[2];
        qx2[g] = pack2(-xa, -xb);
        qy2[g] = pack2(-ya, -yb);
        qz2[g] = pack2(-za, -zb);
        qc2[g] = pack2(0.5f * (xa * xa + ya * ya + za * za),
                       0.5f * (xb * xb + yb * yb + zb * zb));
        rm[2 * g]     = 3.4e38f;
        rm[2 * g + 1] = 3.4e38f;
    }
    __syncthreads();

    const int w    = tid >> 5;
    const int lane = tid & 31;
    const ulonglong2* __restrict__ pXY1 = reinterpret_cast<const ulonglong2*>(sXY1);
    const ulonglong2* __restrict__ pZC1 = reinterpret_cast<const ulonglong2*>(sZC1);
    const ulonglong2* __restrict__ pXY2 = reinterpret_cast<const ulonglong2*>(sXY2);
    const ulonglong2* __restrict__ pZC2 = reinterpret_cast<const ulonglong2*>(sZC2);
    float2* __restrict__ cmrow = scm[w];

    // Lane-skewed pair walk: at each step lanes hold distinct jp (npairs >= 32)
    // -> race-free col-min RMW in the warp's private row.
    int jp = lane;
#pragma unroll 2
    for (int s = 0; s < npairs; s++) {
        ulonglong2 vxy1 = pXY1[jp];     // {x0,x1},{y0,y1}
        ulonglong2 vzc1 = pZC1[jp];     // {z0,z1},{c0,c1}
        ulonglong2 vxy2 = pXY2[jp];     // {x1,x0},{y1,y0}
        ulonglong2 vzc2 = pZC2[jp];     // {z1,z0},{c1,c0}
        float2 cm = cmrow[jp];
        float cp0 = cm.x, cp1 = cm.y;
#pragma unroll
        for (int g = 0; g < NGRP; g++) {
            u64 h1 = fma2(qz2[g], vzc1.x, add2(qc2[g], vzc1.y));
            h1 = fma2(qy2[g], vxy1.y, h1);
            h1 = fma2(qx2[g], vxy1.x, h1);
            u64 h2 = fma2(qz2[g], vzc2.x, add2(qc2[g], vzc2.y));
            h2 = fma2(qy2[g], vxy2.y, h2);
            h2 = fma2(qx2[g], vxy2.x, h2);
            float a0, b1; unpack2(h1, a0, b1);   // w(A,p0), w(B,p1)
            float a1, b0; unpack2(h2, a1, b0);   // w(A,p1), w(B,p0)
            rm[2 * g]     = fminf(rm[2 * g],     fminf(a0, a1));
            rm[2 * g + 1] = fminf(rm[2 * g + 1], fminf(b0, b1));
            cp0 = fminf(cp0, fminf(a0, b0));
            cp1 = fminf(cp1, fminf(a1, b1));
        }
        cmrow[jp] = make_float2(cp0, cp1);
        jp++; if (jp == npairs) jp = 0;
    }
    __syncthreads();

    // Row-min partials, coalesced.
    float* rout = g_rowpart + ((size_t)(b * JSPLITS + js)) * NPTS + ibase;
#pragma unroll
    for (int k = 0; k < QPT; k++)
        rout[tid + k * THREADS] = rm[k];

    // Col-min partials: combine warp rows, float2 per pair.
    if (tid < npairs) {
        float2 m = scm[0][tid];
#pragma unroll
        for (int u = 1; u < THREADS / 32; u++) {
            float2 v = scm[u][tid];
            m.x = fminf(m.x, v.x);
            m.y = fminf(m.y, v.y);
        }
        float2* cout = reinterpret_cast<float2*>(
            g_colpart + ((size_t)(b * ITILES + it)) * NPTS + 2 * (pstart + tid));
        cout[0] = m;
    }
}

// Fused reduce: 64 blocks x 128 threads; each thread owns ONE float4 task
// (4 adjacent queries). Row tasks: 4096 (min over 55 splits, MLP-11 batched);
// col tasks: 4096 (min over 4 splits). Last block sums 64 block sums.
__global__ __launch_bounds__(128)
void chamfer_reduce(float* __restrict__ out) {
    __shared__ float ssum[128];
    __shared__ int s_last;
    const int task = blockIdx.x * 128 + threadIdx.x;   // 0..8191
    float4 mv = make_float4(3.4e38f, 3.4e38f, 3.4e38f, 3.4e38f);

    if (task < 4096) {
        // Row side: b = task/2048, f4 = task%2048 (float4 index within batch).
        const int b  = task >> 11;
        const int f4 = task & 2047;
        const float4* p = reinterpret_cast<const float4*>(
            g_rowpart + (size_t)b * JSPLITS * NPTS) + f4;
        const int STR4 = NPTS / 4;   // float4 stride between splits
        int t = 0;
#pragma unroll 1
        for (int c = 0; c < 5; c++) {               // 5 chunks: 11,11,11,11,11 -> 55
            float4 v[11];
#pragma unroll
            for (int u = 0; u < 11; u++) v[u] = p[(size_t)(t + u) * STR4];
#pragma unroll
            for (int u = 0; u < 11; u++) {
                mv.x = fminf(mv.x, v[u].x);
                mv.y = fminf(mv.y, v[u].y);
                mv.z = fminf(mv.z, v[u].z);
                mv.w = fminf(mv.w, v[u].w);
            }
            t += 11;
        }
    } else {
        const int q  = task - 4096;
        const int b  = q >> 11;
        const int f4 = q & 2047;
        const float4* p = reinterpret_cast<const float4*>(
            g_colpart + (size_t)b * ITILES * NPTS) + f4;
        const int STR4 = NPTS / 4;
        float4 v[ITILES];
#pragma unroll
        for (int u = 0; u < ITILES; u++) v[u] = p[(size_t)u * STR4];
#pragma unroll
        for (int u = 0; u < ITILES; u++) {
            mv.x = fminf(mv.x, v[u].x);
            mv.y = fminf(mv.y, v[u].y);
            mv.z = fminf(mv.z, v[u].z);
            mv.w = fminf(mv.w, v[u].w);
        }
    }

    float acc = sqrtf(fmaxf(2.0f * mv.x, 0.0f)) + sqrtf(fmaxf(2.0f * mv.y, 0.0f))
              + sqrtf(fmaxf(2.0f * mv.z, 0.0f)) + sqrtf(fmaxf(2.0f * mv.w, 0.0f));
    ssum[threadIdx.x] = acc;
    __syncthreads();
    for (int s = 64; s > 0; s >>= 1) {
        if (threadIdx.x < s) ssum[threadIdx.x] += ssum[threadIdx.x + s];
        __syncthreads();
    }
    if (threadIdx.x == 0) {
        g_blocksum[blockIdx.x] = ssum[0];
        __threadfence();
        unsigned t = atomicAdd(&g_done, 1u);
        s_last = (t == RBLOCKS - 1u);
    }
    __syncthreads();
    if (s_last) {
        volatile float* bs = g_blocksum;
        ssum[threadIdx.x] = (threadIdx.x < RBLOCKS) ? bs[threadIdx.x] : 0.0f;
        __syncthreads();
        for (int s = 64; s > 0; s >>= 1) {
            if (threadIdx.x < s) ssum[threadIdx.x] += ssum[threadIdx.x + s];
            __syncthreads();
        }
        if (threadIdx.x == 0) {
            out[0] = ssum[0] / (float)(BATCH * NPTS);
            g_done = 0;   // reset for next graph replay
        }
    }
}

extern "C" void kernel_launch(void* const* d_in, const int* in_sizes, int n_in,
                              void* d_out, int out_size) {
    const float* pred = (const float*)d_in[0];
    const float* gt   = (const float*)d_in[1];
    float* out        = (float*)d_out;

    chamfer_pass<<<NCTA, THREADS>>>(pred, gt);
    chamfer_reduce<<<RBLOCKS, 128>>>(out);
}

// round 14
// speedup vs baseline: 1.0928x; 1.0928x over previous
#include <cuda_runtime.h>

// Chamfer distance, B=2, N=8192. Symmetric pass (unchanged): each pair computed
// once, feeds both row-min (per-gt) and col-min (per-pred), dual-order f32x2.
// Reduce: split-parallel (8 threads/query on row side) so latency is hidden by
// warp count, not per-thread MLP. 2 launches; done-counter final sum.

#define BATCH   2
#define NPTS    8192
#define THREADS 256
#define QPT     8                    // queries per thread
#define NGRP    (QPT / 2)            // 4 packed query groups
#define IBLK    (THREADS * QPT)      // 2048 gt rows per CTA
#define ITILES  (NPTS / IBLK)        // 4
#define JSPLITS 55
#define TOTP    (NPTS / 2)           // 4096 pred pairs per batch
#define MAXP    75                   // ceil(4096/55)
#define NCTA    (BATCH * ITILES * JSPLITS)   // 440 <= 444 @3/SM -> one wave
#define RROW    512                  // row-side reduce blocks (32 queries each)
#define RCOL    64                   // col-side reduce blocks (256 queries each)
#define RBLOCKS (RROW + RCOL)        // 576

__device__ float    g_rowpart[BATCH * JSPLITS * NPTS];   // 3.6 MB
__device__ float    g_colpart[BATCH * ITILES  * NPTS];   // 0.25 MB
__device__ float    g_blocksum[RBLOCKS];
__device__ unsigned g_done;          // zero-init; self-resets each call

typedef unsigned long long u64;

__device__ __forceinline__ u64 pack2(float lo, float hi) {
    u64 d; asm("mov.b64 %0, {%1,%2};" : "=l"(d) : "f"(lo), "f"(hi)); return d;
}
__device__ __forceinline__ void unpack2(u64 d, float& lo, float& hi) {
    asm("mov.b64 {%0,%1}, %2;" : "=f"(lo), "=f"(hi) : "l"(d));
}
__device__ __forceinline__ u64 fma2(u64 a, u64 b, u64 c) {
    u64 d; asm("fma.rn.f32x2 %0, %1, %2, %3;" : "=l"(d) : "l"(a), "l"(b), "l"(c));
    return d;
}
__device__ __forceinline__ u64 add2(u64 a, u64 b) {
    u64 d; asm("add.rn.f32x2 %0, %1, %2;" : "=l"(d) : "l"(a), "l"(b));
    return d;
}

__global__ __launch_bounds__(THREADS, 3)
void chamfer_pass(const float* __restrict__ pred, const float* __restrict__ gt) {
    const int bid = blockIdx.x;
    const int b   = bid / (ITILES * JSPLITS);
    const int r   = bid - b * (ITILES * JSPLITS);
    const int it  = r / JSPLITS;
    const int js  = r - it * JSPLITS;
    const int ibase  = it * IBLK;
    const int pstart = (js * TOTP) / JSPLITS;
    const int pend   = ((js + 1) * TOTP) / JSPLITS;
    const int npairs = pend - pstart;           // 74 or 75 (>= 32 for lane-skew)
    const int tid = threadIdx.x;

    // 16B-stride arrays (conflict-free under lane-consecutive jp):
    __shared__ float4 sXY1[MAXP];   // {x0,x1,y0,y1}
    __shared__ float4 sZC1[MAXP];   // {z0,z1,c0,c1}
    __shared__ float4 sXY2[MAXP];   // {x1,x0,y1,y0}
    __shared__ float4 sZC2[MAXP];   // {z1,z0,c1,c0}
    __shared__ float2 scm[THREADS / 32][MAXP]; // per-warp col-min {p0,p1}

    if (tid < npairs) {
        const float* p = pred + ((size_t)b * NPTS + 2 * (pstart + tid)) * 3;
        float x0 = p[0], y0 = p[1], z0 = p[2];
        float x1 = p[3], y1 = p[4], z1 = p[5];
        float c0 = 0.5f * (x0 * x0 + y0 * y0 + z0 * z0);
        float c1 = 0.5f * (x1 * x1 + y1 * y1 + z1 * z1);
        sXY1[tid] = make_float4(x0, x1, y0, y1);
        sZC1[tid] = make_float4(z0, z1, c0, c1);
        sXY2[tid] = make_float4(x1, x0, y1, y0);
        sZC2[tid] = make_float4(z1, z0, c1, c0);
    }
    if (tid < MAXP) {
#pragma unroll
        for (int u = 0; u < THREADS / 32; u++)
            scm[u][tid] = make_float2(3.4e38f, 3.4e38f);
    }

    // Queries (gt): two different queries per u64 (A = slot 2g, B = slot 2g+1).
    u64 qx2[NGRP], qy2[NGRP], qz2[NGRP], qc2[NGRP];
    float rm[QPT];
#pragma unroll
    for (int g = 0; g < NGRP; g++) {
        const float* qa = gt + ((size_t)b * NPTS + ibase + tid + (2 * g) * THREADS) * 3;
        const float* qb = gt + ((size_t)b * NPTS + ibase + tid + (2 * g + 1) * THREADS) * 3;
        float xa = qa[0], ya = qa[1], za = qa[2];
        float xb = qb[0], yb = qb[1], zb = qb[2];
        qx2[g] = pack2(-xa, -xb);
        qy2[g] = pack2(-ya, -yb);
        qz2[g] = pack2(-za, -zb);
        qc2[g] = pack2(0.5f * (xa * xa + ya * ya + za * za),
                       0.5f * (xb * xb + yb * yb + zb * zb));
        rm[2 * g]     = 3.4e38f;
        rm[2 * g + 1] = 3.4e38f;
    }
    __syncthreads();

    const int w    = tid >> 5;
    const int lane = tid & 31;
    const ulonglong2* __restrict__ pXY1 = reinterpret_cast<const ulonglong2*>(sXY1);
    const ulonglong2* __restrict__ pZC1 = reinterpret_cast<const ulonglong2*>(sZC1);
    const ulonglong2* __restrict__ pXY2 = reinterpret_cast<const ulonglong2*>(sXY2);
    const ulonglong2* __restrict__ pZC2 = reinterpret_cast<const ulonglong2*>(sZC2);
    float2* __restrict__ cmrow = scm[w];

    // Lane-skewed pair walk: at each step lanes hold distinct jp (npairs >= 32)
    // -> race-free col-min RMW in the warp's private row.
    int jp = lane;
#pragma unroll 2
    for (int s = 0; s < npairs; s++) {
        ulonglong2 vxy1 = pXY1[jp];     // {x0,x1},{y0,y1}
        ulonglong2 vzc1 = pZC1[jp];     // {z0,z1},{c0,c1}
        ulonglong2 vxy2 = pXY2[jp];     // {x1,x0},{y1,y0}
        ulonglong2 vzc2 = pZC2[jp];     // {z1,z0},{c1,c0}
        float2 cm = cmrow[jp];
        float cp0 = cm.x, cp1 = cm.y;
#pragma unroll
        for (int g = 0; g < NGRP; g++) {
            u64 h1 = fma2(qz2[g], vzc1.x, add2(qc2[g], vzc1.y));
            h1 = fma2(qy2[g], vxy1.y, h1);
            h1 = fma2(qx2[g], vxy1.x, h1);
            u64 h2 = fma2(qz2[g], vzc2.x, add2(qc2[g], vzc2.y));
            h2 = fma2(qy2[g], vxy2.y, h2);
            h2 = fma2(qx2[g], vxy2.x, h2);
            float a0, b1; unpack2(h1, a0, b1);   // w(A,p0), w(B,p1)
            float a1, b0; unpack2(h2, a1, b0);   // w(A,p1), w(B,p0)
            rm[2 * g]     = fminf(rm[2 * g],     fminf(a0, a1));
            rm[2 * g + 1] = fminf(rm[2 * g + 1], fminf(b0, b1));
            cp0 = fminf(cp0, fminf(a0, b0));
            cp1 = fminf(cp1, fminf(a1, b1));
        }
        cmrow[jp] = make_float2(cp0, cp1);
        jp++; if (jp == npairs) jp = 0;
    }
    __syncthreads();

    // Row-min partials, coalesced.
    float* rout = g_rowpart + ((size_t)(b * JSPLITS + js)) * NPTS + ibase;
#pragma unroll
    for (int k = 0; k < QPT; k++)
        rout[tid + k * THREADS] = rm[k];

    // Col-min partials: combine warp rows, float2 per pair.
    if (tid < npairs) {
        float2 m = scm[0][tid];
#pragma unroll
        for (int u = 1; u < THREADS / 32; u++) {
            float2 v = scm[u][tid];
            m.x = fminf(m.x, v.x);
            m.y = fminf(m.y, v.y);
        }
        float2* cout = reinterpret_cast<float2*>(
            g_colpart + ((size_t)(b * ITILES + it)) * NPTS + 2 * (pstart + tid));
        cout[0] = m;
    }
}

// Split-parallel reduce. Row blocks (0..511): 32 queries x 8 split-groups per
// block; each thread scans splits s0, s0+8, ... (<=7 coalesced loads). Col
// blocks (512..575): 256 queries, 4 loads each. Fixed-order sums throughout.
__global__ __launch_bounds__(256)
void chamfer_reduce(float* __restrict__ out) {
    __shared__ float ssum[256];
    __shared__ int s_last;
    const int tid = threadIdx.x;
    float blocktotal;

    if (blockIdx.x < RROW) {
        const int qid = blockIdx.x * 32 + (tid & 31);   // 0..16383
        const int b = qid >> 13, i = qid & (NPTS - 1);
        const int s0 = tid >> 5;                        // split group 0..7
        float mv = 3.4e38f;
#pragma unroll
        for (int k = 0; k < 7; k++) {
            int sp = s0 + (k << 3);
            if (sp < JSPLITS)
                mv = fminf(mv, g_rowpart[((size_t)(b * JSPLITS + sp)) * NPTS + i]);
        }
        ssum[tid] = mv;
        __syncthreads();
        if (tid < 32) {
            float m = ssum[tid];
#pragma unroll
            for (int u = 1; u < 8; u++) m = fminf(m, ssum[tid + 32 * u]);
            float acc = sqrtf(fmaxf(2.0f * m, 0.0f));
#pragma unroll
            for (int o = 16; o; o >>= 1)
                acc += __shfl_xor_sync(0xffffffffu, acc, o);
            if (tid == 0) ssum[0] = acc;
        }
        __syncthreads();
        blocktotal = ssum[0];
    } else {
        const int qid = (blockIdx.x - RROW) * 256 + tid;   // 0..16383
        const int b = qid >> 13, j = qid & (NPTS - 1);
        float mv = 3.4e38f;
#pragma unroll
        for (int u = 0; u < ITILES; u++)
            mv = fminf(mv, g_colpart[((size_t)(b * ITILES + u)) * NPTS + j]);
        ssum[tid] = sqrtf(fmaxf(2.0f * mv, 0.0f));
        __syncthreads();
        for (int s = 128; s > 0; s >>= 1) {
            if (tid < s) ssum[tid] += ssum[tid + s];
            __syncthreads();
        }
        blocktotal = ssum[0];
    }

    if (tid == 0) {
        g_blocksum[blockIdx.x] = blocktotal;
        __threadfence();
        unsigned t = atomicAdd(&g_done, 1u);
        s_last = (t == RBLOCKS - 1u);
    }
    __syncthreads();
    if (s_last) {
        volatile float* bs = g_blocksum;
        float a = bs[tid] + bs[tid + 256];
        if (tid < RBLOCKS - 512) a += bs[tid + 512];
        ssum[tid] = a;
        __syncthreads();
        for (int s = 128; s > 0; s >>= 1) {
            if (tid < s) ssum[tid] += ssum[tid + s];
            __syncthreads();
        }
        if (tid == 0) {
            out[0] = ssum[0] / (float)(BATCH * NPTS);
            g_done = 0;   // reset for next graph replay
        }
    }
}

extern "C" void kernel_launch(void* const* d_in, const int* in_sizes, int n_in,
                              void* d_out, int out_size) {
    const float* pred = (const float*)d_in[0];
    const float* gt   = (const float*)d_in[1];
    float* out        = (float*)d_out;

    chamfer_pass<<<NCTA, THREADS>>>(pred, gt);
    chamfer_reduce<<<RBLOCKS, 256>>>(out);
}